// round 1
// baseline (speedup 1.0000x reference)
#include <cuda_runtime.h>

// Problem constants (fixed shapes from the reference).
#define Bc   2
#define Tc   2048
#define Dc   1024
#define Hc   16
#define NDc  64
#define BHc  (Bc*Hc)

// Scratch (static __device__ arrays — allowed per harness rules).
__device__ float g_QH[BHc * Tc * NDc];          // [b*H+h][t][nd]
__device__ float g_KH[BHc * Tc * NDc];
__device__ float g_VH[BHc * Tc * NDc];
__device__ float g_O [Bc * Tc * Dc];            // [b][t][h*nd+d]  == [B,T,D]
__device__ float g_inv[BHc * Tc];               // 1 / column-sum
__device__ float g_E[(size_t)BHc * Tc * Tc];    // exp(z), lower-tri band written

// ---------------------------------------------------------------------------
// Generic Y = X @ W^T + b  (M x K) * (N x K)^T, N = Dc = 1024.
// 64x64 tile, BK=16, 256 threads, 4x4 per thread.
// split=1: scatter output into per-head layout [b*H+h][t][nd].
// ---------------------------------------------------------------------------
__global__ __launch_bounds__(256)
void proj_kernel(const float* __restrict__ X, const float* __restrict__ W,
                 const float* __restrict__ bias, float* __restrict__ Y,
                 int K, int split)
{
    __shared__ __align__(16) float As[16][68];
    __shared__ __align__(16) float Bs[16][68];
    const int bm = blockIdx.y * 64;
    const int bn = blockIdx.x * 64;
    const int tid = threadIdx.x;
    const int tx = tid & 15, ty = tid >> 4;
    const int lr = tid >> 4, lc = tid & 15;
    float acc[4][4] = {};

    for (int k0 = 0; k0 < K; k0 += 16) {
        #pragma unroll
        for (int i = 0; i < 4; i++) {
            As[lc][lr + 16*i] = X[(size_t)(bm + lr + 16*i) * K + k0 + lc];
            Bs[lc][lr + 16*i] = W[(size_t)(bn + lr + 16*i) * K + k0 + lc];
        }
        __syncthreads();
        #pragma unroll
        for (int kk = 0; kk < 16; kk++) {
            float4 a  = *(const float4*)&As[kk][ty * 4];
            float4 bv = *(const float4*)&Bs[kk][tx * 4];
            float av[4] = {a.x, a.y, a.z, a.w};
            float bw[4] = {bv.x, bv.y, bv.z, bv.w};
            #pragma unroll
            for (int i = 0; i < 4; i++)
                #pragma unroll
                for (int j = 0; j < 4; j++)
                    acc[i][j] += av[i] * bw[j];
        }
        __syncthreads();
    }

    #pragma unroll
    for (int i = 0; i < 4; i++) {
        int m = bm + ty * 4 + i;
        #pragma unroll
        for (int j = 0; j < 4; j++) {
            int n = bn + tx * 4 + j;
            float v = acc[i][j] + bias[n];
            if (split) {
                int b = m >> 11;          // m / Tc
                int t = m & (Tc - 1);
                int h = n >> 6;           // n / NDc
                int d = n & (NDc - 1);
                g_QH[0];                  // no-op; keeps globals referenced path simple
                Y[(size_t)((b * Hc + h) * Tc + t) * NDc + d] = v;
            } else {
                Y[(size_t)m * Dc + n] = v;
            }
        }
    }
}

// ---------------------------------------------------------------------------
// E[bh][q][k] = exp( (qh[q] . kh[k]) / 8 )  for k <= q, else 0 (diagonal tile).
// Blocks with kt > qt skipped entirely (never read downstream).
// ---------------------------------------------------------------------------
__global__ __launch_bounds__(256)
void score_kernel()
{
    const int kt = blockIdx.x;
    const int qt = blockIdx.y;
    const int bh = blockIdx.z;
    if (kt > qt) return;

    const float* Qp = g_QH + (size_t)bh * Tc * NDc;
    const float* Kp = g_KH + (size_t)bh * Tc * NDc;
    float*       Ep = g_E  + (size_t)bh * Tc * Tc;

    __shared__ __align__(16) float Qs[16][68];
    __shared__ __align__(16) float Ks[16][68];
    const int tid = threadIdx.x;
    const int tx = tid & 15, ty = tid >> 4;
    const int lr = tid >> 4, lc = tid & 15;
    float acc[4][4] = {};

    #pragma unroll
    for (int k0 = 0; k0 < NDc; k0 += 16) {
        #pragma unroll
        for (int i = 0; i < 4; i++) {
            Qs[lc][lr + 16*i] = Qp[(size_t)(qt * 64 + lr + 16*i) * NDc + k0 + lc];
            Ks[lc][lr + 16*i] = Kp[(size_t)(kt * 64 + lr + 16*i) * NDc + k0 + lc];
        }
        __syncthreads();
        #pragma unroll
        for (int kk = 0; kk < 16; kk++) {
            float4 a  = *(const float4*)&Qs[kk][ty * 4];
            float4 bv = *(const float4*)&Ks[kk][tx * 4];
            float av[4] = {a.x, a.y, a.z, a.w};
            float bw[4] = {bv.x, bv.y, bv.z, bv.w};
            #pragma unroll
            for (int i = 0; i < 4; i++)
                #pragma unroll
                for (int j = 0; j < 4; j++)
                    acc[i][j] += av[i] * bw[j];
        }
        __syncthreads();
    }

    #pragma unroll
    for (int i = 0; i < 4; i++) {
        int q = qt * 64 + ty * 4 + i;
        #pragma unroll
        for (int j = 0; j < 4; j++) {
            int kcol = kt * 64 + tx * 4 + j;
            float v = (kcol <= q) ? __expf(acc[i][j] * 0.125f) : 0.0f;
            Ep[(size_t)q * Tc + kcol] = v;
        }
    }
}

// ---------------------------------------------------------------------------
// inv[bh][k] = 1 / sum_{q >= k} E[bh][q][k].  Deterministic serial column sum.
// Only reads the written lower-triangular band (q >= (k & ~63)).
// ---------------------------------------------------------------------------
__global__ __launch_bounds__(256)
void colsum_kernel()
{
    const int bh = blockIdx.y;
    const int k  = blockIdx.x * 256 + threadIdx.x;
    const float* Ep = g_E + (size_t)bh * Tc * Tc;
    float s = 0.0f;
    for (int q = k & ~63; q < Tc; q++)
        s += Ep[(size_t)q * Tc + k];
    g_inv[bh * Tc + k] = 1.0f / s;
}

// ---------------------------------------------------------------------------
// O[q][d] = sum_{k <= q} (E[q][k] * inv[k]) * V[k][d].   N = nd = 64 (full).
// Output written directly in [B, T, D] layout for the final projection.
// ---------------------------------------------------------------------------
__global__ __launch_bounds__(256)
void attnv_kernel()
{
    const int qt = blockIdx.x;
    const int bh = blockIdx.y;
    const float* Ep   = g_E   + (size_t)bh * Tc * Tc;
    const float* Vp   = g_VH  + (size_t)bh * Tc * NDc;
    const float* invp = g_inv + (size_t)bh * Tc;

    __shared__ __align__(16) float Es[16][68];
    __shared__ __align__(16) float Vs[16][68];
    const int tid = threadIdx.x;
    const int tx = tid & 15, ty = tid >> 4;
    const int lr = tid >> 4, lc = tid & 15;   // E loads: 16 rows x 16 k
    const int vr = tid >> 6, vc = tid & 63;   // V loads:  4 rows x 64 d
    float acc[4][4] = {};

    const int kmax = (qt + 1) * 64;
    for (int k0 = 0; k0 < kmax; k0 += 16) {
        #pragma unroll
        for (int i = 0; i < 4; i++)
            Es[lc][lr + 16*i] =
                Ep[(size_t)(qt * 64 + lr + 16*i) * Tc + k0 + lc] * invp[k0 + lc];
        #pragma unroll
        for (int i = 0; i < 4; i++)
            Vs[vr + 4*i][vc] = Vp[(size_t)(k0 + vr + 4*i) * NDc + vc];
        __syncthreads();
        #pragma unroll
        for (int kk = 0; kk < 16; kk++) {
            float4 a  = *(const float4*)&Es[kk][ty * 4];
            float4 bv = *(const float4*)&Vs[kk][tx * 4];
            float av[4] = {a.x, a.y, a.z, a.w};
            float bw[4] = {bv.x, bv.y, bv.z, bv.w};
            #pragma unroll
            for (int i = 0; i < 4; i++)
                #pragma unroll
                for (int j = 0; j < 4; j++)
                    acc[i][j] += av[i] * bw[j];
        }
        __syncthreads();
    }

    const int b = bh >> 4;          // bh / Hc
    const int h = bh & (Hc - 1);
    #pragma unroll
    for (int i = 0; i < 4; i++) {
        int q = qt * 64 + ty * 4 + i;
        #pragma unroll
        for (int j = 0; j < 4; j++) {
            int d = tx * 4 + j;
            g_O[(size_t)(b * Tc + q) * Dc + h * NDc + d] = acc[i][j];
        }
    }
}

// ---------------------------------------------------------------------------
extern "C" void kernel_launch(void* const* d_in, const int* in_sizes, int n_in,
                              void* d_out, int out_size)
{
    const float* q  = (const float*)d_in[0];
    const float* k  = (const float*)d_in[1];
    const float* v  = (const float*)d_in[2];
    const float* Wq = (const float*)d_in[3];
    const float* bq = (const float*)d_in[4];
    const float* Wk = (const float*)d_in[5];
    const float* bk = (const float*)d_in[6];
    const float* Wv = (const float*)d_in[7];
    const float* bv = (const float*)d_in[8];
    const float* Wc = (const float*)d_in[9];
    const float* bc = (const float*)d_in[10];
    float* out = (float*)d_out;

    float *pQH, *pKH, *pVH, *pO;
    cudaGetSymbolAddress((void**)&pQH, g_QH);
    cudaGetSymbolAddress((void**)&pKH, g_KH);
    cudaGetSymbolAddress((void**)&pVH, g_VH);
    cudaGetSymbolAddress((void**)&pO,  g_O);

    dim3 tpb(256);
    dim3 gproj(Dc / 64, (Bc * Tc) / 64);   // 16 x 64 blocks

    proj_kernel<<<gproj, tpb>>>(q, Wq, bq, pQH, Dc, 1);
    proj_kernel<<<gproj, tpb>>>(k, Wk, bk, pKH, Dc, 1);
    proj_kernel<<<gproj, tpb>>>(v, Wv, bv, pVH, Dc, 1);

    score_kernel<<<dim3(Tc / 64, Tc / 64, BHc), tpb>>>();
    colsum_kernel<<<dim3(Tc / 256, BHc), tpb>>>();
    attnv_kernel<<<dim3(Tc / 64, BHc), tpb>>>();

    proj_kernel<<<gproj, tpb>>>(pO, Wc, bc, out, Dc, 0);
}